// round 13
// baseline (speedup 1.0000x reference)
#include <cuda_runtime.h>
#include <cuda_bf16.h>
#include <math.h>
#include <stdint.h>

#define BB 4
#define CC 192
#define NN 3136
#define NP 3200      // padded rows (25 * 128)
#define KK 9
#define TT 16
#define NT 25        // number of 128-wide tiles
#define OO 384
#define OO2 768
#define FINF 3.402823466e38f

typedef unsigned long long u64;

// ---------------- scratch (static device globals) ----------------
__device__ float          g_xt[(size_t)BB * NN * CC];      // fp32 normalized, [row][c]
__device__ __nv_bfloat16  g_nhi[(size_t)BB * NP * CC];     // normalized hi
__device__ __nv_bfloat16  g_nlo[(size_t)BB * NP * CC];     // normalized lo
__device__ __nv_bfloat16  g_xhi[(size_t)BB * NP * CC];     // raw x hi
__device__ __nv_bfloat16  g_xlo[(size_t)BB * NP * CC];     // raw x lo
__device__ __nv_bfloat16  g_whi[OO2 * CC];
__device__ __nv_bfloat16  g_wlo[OO2 * CC];
__device__ float          g_sqn[BB * NN];
__device__ float2         g_sqdf[BB * NN];
__device__ u64            g_pck[(size_t)BB * NN * NT * TT];  // per-tile candidate keys
__device__ int            g_cand[BB * NN * TT];
__device__ int            g_idx[BB * NN * KK];
__device__ float          g_ab[(size_t)BB * NN * OO2];

// ---------------- ordered-float encoding ----------------
__device__ __forceinline__ unsigned encf(float v) {
    unsigned u = __float_as_uint(v);
    return u ^ ((u & 0x80000000u) ? 0xFFFFFFFFu : 0x80000000u);
}

// ---------------- double-float helpers ----------------
__device__ __forceinline__ void twosum(float a, float b, float& s, float& e) {
    s = a + b;
    float bp = s - a;
    e = (a - (s - bp)) + (b - bp);
}
__device__ __forceinline__ void df_accum(float& hi, float& lo, float p, float pe) {
    float s, e;
    twosum(hi, p, s, e);
    lo += e + pe;
    hi = s;
}
__device__ __forceinline__ void df_nrm(float& hi, float& lo) {
    float s, e;
    twosum(hi, lo, s, e);
    hi = s; lo = e;
}
__device__ __forceinline__ void df_add2(float ah, float al, float bh, float bl, float& h, float& l) {
    float s, e;
    twosum(ah, bh, s, e);
    e += al + bl;
    twosum(s, e, h, l);
}

// ---------------- 1) normalize (vectorized writes) ----------------
__global__ void normalize_kernel(const float* __restrict__ x) {
    int b = blockIdx.y;
    int n = blockIdx.x * 256 + threadIdx.x;
    if (n >= NP) return;
    size_t rowp = ((size_t)b * NP + n) * CC;
    if (n >= NN) {   // zero padding rows, 16B stores
        uint4 z = make_uint4(0, 0, 0, 0);
        #pragma unroll 4
        for (int i = 0; i < CC / 8; i++) {
            reinterpret_cast<uint4*>(g_nhi + rowp)[i] = z;
            reinterpret_cast<uint4*>(g_nlo + rowp)[i] = z;
            reinterpret_cast<uint4*>(g_xhi + rowp)[i] = z;
            reinterpret_cast<uint4*>(g_xlo + rowp)[i] = z;
        }
        return;
    }
    const float* xb = x + (size_t)b * CC * NN + n;
    float hi = 0.f, lo = 0.f;
    #pragma unroll 2
    for (int c0 = 0; c0 < CC; c0 += 8) {
        float v[8];
        __nv_bfloat16 h8[8], l8[8];
        #pragma unroll
        for (int j = 0; j < 8; j++) v[j] = xb[(size_t)(c0 + j) * NN];
        #pragma unroll
        for (int j = 0; j < 8; j++) {
            float p = v[j] * v[j];
            float pe = fmaf(v[j], v[j], -p);
            df_accum(hi, lo, p, pe);
            h8[j] = __float2bfloat16(v[j]);
            l8[j] = __float2bfloat16(v[j] - __bfloat162float(h8[j]));
        }
        *reinterpret_cast<uint4*>(g_xhi + rowp + c0) = *reinterpret_cast<uint4*>(h8);
        *reinterpret_cast<uint4*>(g_xlo + rowp + c0) = *reinterpret_cast<uint4*>(l8);
    }
    float den = fmaxf(sqrtf(hi + lo), 1e-12f);
    float* xtb = g_xt + ((size_t)b * NN + n) * CC;
    float shi = 0.f, slo = 0.f;
    #pragma unroll 2
    for (int c0 = 0; c0 < CC; c0 += 8) {
        float v[8];
        __nv_bfloat16 h8[8], l8[8];
        #pragma unroll
        for (int j = 0; j < 8; j++) v[j] = __fdiv_rn(xb[(size_t)(c0 + j) * NN], den);
        #pragma unroll
        for (int j = 0; j < 8; j++) {
            float p = v[j] * v[j];
            float pe = fmaf(v[j], v[j], -p);
            df_accum(shi, slo, p, pe);
            h8[j] = __float2bfloat16(v[j]);
            l8[j] = __float2bfloat16(v[j] - __bfloat162float(h8[j]));
        }
        *reinterpret_cast<uint4*>(g_nhi + rowp + c0) = *reinterpret_cast<uint4*>(h8);
        *reinterpret_cast<uint4*>(g_nlo + rowp + c0) = *reinterpret_cast<uint4*>(l8);
        *reinterpret_cast<float4*>(xtb + c0)     = make_float4(v[0], v[1], v[2], v[3]);
        *reinterpret_cast<float4*>(xtb + c0 + 4) = make_float4(v[4], v[5], v[6], v[7]);
    }
    df_nrm(shi, slo);
    g_sqn[b * NN + n] = shi + slo;
    g_sqdf[b * NN + n] = make_float2(shi, slo);
}

// ---------------- 2) weight prep ----------------
__global__ void wprep_kernel(const float* __restrict__ w) {
    int i = blockIdx.x * 256 + threadIdx.x;
    if (i >= OO2 * CC) return;
    int op = i / CC;
    int c = i % CC;
    float v;
    if (op < OO) v = w[op * (2 * CC) + c] - w[op * (2 * CC) + CC + c];
    else         v = w[(op - OO) * (2 * CC) + CC + c];
    __nv_bfloat16 h = __float2bfloat16(v);
    g_whi[i] = h;
    g_wlo[i] = __float2bfloat16(v - __bfloat162float(h));
}

// ---------------- 3) split-bf16 mma.sync GEMM, cp.async pipelined ----------------
// MODE 0: dist tiles -> per-tile top-16 candidate keys (no gmem dist). MODE 1: ab gemm.
__device__ __forceinline__ void mma_bf16(float c[4], uint32_t a0, uint32_t a1, uint32_t a2, uint32_t a3,
                                         uint32_t b0, uint32_t b1) {
    asm volatile("mma.sync.aligned.m16n8k16.row.col.f32.bf16.bf16.f32 "
                 "{%0,%1,%2,%3}, {%4,%5,%6,%7}, {%8,%9}, {%0,%1,%2,%3};"
                 : "+f"(c[0]), "+f"(c[1]), "+f"(c[2]), "+f"(c[3])
                 : "r"(a0), "r"(a1), "r"(a2), "r"(a3), "r"(b0), "r"(b1));
}

__device__ __forceinline__ uint32_t smem_u32(const void* p) {
    uint32_t a;
    asm("{ .reg .u64 t; cvta.to.shared.u64 t, %1; cvt.u32.u64 %0, t; }" : "=r"(a) : "l"(p));
    return a;
}

// per-thread sorted(ascending) top-16 of u64 keys.
// Threshold kept in ENCODED uint domain: sentinel ~0ull -> hi15=0xFFFFFFFF accepts all.
struct Top16 {
    u64 k[16];
    unsigned hi15;
    __device__ __forceinline__ void init() {
        #pragma unroll
        for (int j = 0; j < 16; j++) k[j] = ~0ull;
        hi15 = 0xFFFFFFFFu;
    }
    __device__ __forceinline__ void push(float v, unsigned gidx) {
        unsigned e = encf(v);
        if (e < hi15) {
            k[15] = ((u64)e << 32) | gidx;
            #pragma unroll
            for (int j = 15; j >= 1; j--) {
                if (k[j] < k[j - 1]) { u64 t = k[j]; k[j] = k[j - 1]; k[j - 1] = t; }
            }
            hi15 = (unsigned)(k[15] >> 32);
        }
    }
};

#define SSTR 40            // smem row stride in bf16 (80B)
#define TILEB 10240        // one 128x40 bf16 tile
#define BUFB  40960        // 4 tiles
#define SMEM_DYN 81920     // 2 buffers; epilogue stage reuses [0, 67072)

template <int MODE>
__global__ __launch_bounds__(256) void mma_kernel() {
    extern __shared__ char smem[];
    const int tid = threadIdx.x;
    const int lane = tid & 31;
    const int wid = tid >> 5;
    const int warp_m = wid & 1;
    const int warp_n = wid >> 1;
    const int b = blockIdx.z;
    const int r0 = lane >> 2;
    const int c0 = (lane & 3) * 2;

    int ti, tj;
    if (MODE == 0) {
        int t = blockIdx.x;
        ti = 0;
        while (t >= NT - ti) { t -= NT - ti; ti++; }
        tj = ti + t;
    } else {
        ti = blockIdx.y;
        tj = blockIdx.x;
    }
    const int n0 = ti * 128;
    const int c0out = tj * 128;

    const __nv_bfloat16 *srcs[4];
    if (MODE == 0) {
        srcs[0] = g_nhi + ((size_t)b * NP + n0) * CC;
        srcs[1] = g_nlo + ((size_t)b * NP + n0) * CC;
        srcs[2] = g_nhi + ((size_t)b * NP + c0out) * CC;
        srcs[3] = g_nlo + ((size_t)b * NP + c0out) * CC;
    } else {
        srcs[0] = g_xhi + ((size_t)b * NP + n0) * CC;
        srcs[1] = g_xlo + ((size_t)b * NP + n0) * CC;
        srcs[2] = g_whi + (size_t)c0out * CC;
        srcs[3] = g_wlo + (size_t)c0out * CC;
    }

    const uint32_t sbase = smem_u32(smem);

    auto issue = [&](int bi, int ch) {
        const int k0 = ch * 32;
        #pragma unroll
        for (int q = 0; q < 8; q++) {
            const int t4 = q >> 1;
            const int row = ((q & 1) * 256 + tid) >> 2;
            const int seg = tid & 3;
            const __nv_bfloat16* src = srcs[t4] + (size_t)row * CC + k0 + seg * 8;
            uint32_t dst = sbase + bi * BUFB + t4 * TILEB + row * 80 + seg * 16;
            asm volatile("cp.async.cg.shared.global [%0], [%1], 16;" :: "r"(dst), "l"(src) : "memory");
        }
        asm volatile("cp.async.commit_group;" ::: "memory");
    };

    float acc[4][4][4];
    #pragma unroll
    for (int i = 0; i < 4; i++)
        #pragma unroll
        for (int j = 0; j < 4; j++)
            #pragma unroll
            for (int q = 0; q < 4; q++) acc[i][j][q] = 0.f;

    issue(0, 0);
    #pragma unroll 1
    for (int ch = 0; ch < 6; ch++) {
        if (ch + 1 < 6) {
            issue((ch + 1) & 1, ch + 1);
            asm volatile("cp.async.wait_group 1;" ::: "memory");
        } else {
            asm volatile("cp.async.wait_group 0;" ::: "memory");
        }
        __syncthreads();
        {
            const int bi = ch & 1;
            const __nv_bfloat16* sAh = reinterpret_cast<const __nv_bfloat16*>(smem + bi * BUFB);
            const __nv_bfloat16* sAl = reinterpret_cast<const __nv_bfloat16*>(smem + bi * BUFB + TILEB);
            const __nv_bfloat16* sBh = reinterpret_cast<const __nv_bfloat16*>(smem + bi * BUFB + 2 * TILEB);
            const __nv_bfloat16* sBl = reinterpret_cast<const __nv_bfloat16*>(smem + bi * BUFB + 3 * TILEB);
            #pragma unroll
            for (int ks = 0; ks < 32; ks += 16) {
                uint32_t ah[4][4], al[4][4], bh[4][2], bl[4][2];
                #pragma unroll
                for (int mi = 0; mi < 4; mi++) {
                    int ar = warp_m * 64 + mi * 16 + r0;
                    const __nv_bfloat16* pa = sAh + ar * SSTR + ks + c0;
                    ah[mi][0] = *reinterpret_cast<const uint32_t*>(pa);
                    ah[mi][1] = *reinterpret_cast<const uint32_t*>(pa + 8 * SSTR);
                    ah[mi][2] = *reinterpret_cast<const uint32_t*>(pa + 8);
                    ah[mi][3] = *reinterpret_cast<const uint32_t*>(pa + 8 * SSTR + 8);
                    const __nv_bfloat16* pl = sAl + ar * SSTR + ks + c0;
                    al[mi][0] = *reinterpret_cast<const uint32_t*>(pl);
                    al[mi][1] = *reinterpret_cast<const uint32_t*>(pl + 8 * SSTR);
                    al[mi][2] = *reinterpret_cast<const uint32_t*>(pl + 8);
                    al[mi][3] = *reinterpret_cast<const uint32_t*>(pl + 8 * SSTR + 8);
                }
                #pragma unroll
                for (int ni = 0; ni < 4; ni++) {
                    int br = warp_n * 32 + ni * 8 + r0;
                    const __nv_bfloat16* pb = sBh + br * SSTR + ks + c0;
                    bh[ni][0] = *reinterpret_cast<const uint32_t*>(pb);
                    bh[ni][1] = *reinterpret_cast<const uint32_t*>(pb + 8);
                    const __nv_bfloat16* pbl = sBl + br * SSTR + ks + c0;
                    bl[ni][0] = *reinterpret_cast<const uint32_t*>(pbl);
                    bl[ni][1] = *reinterpret_cast<const uint32_t*>(pbl + 8);
                }
                #pragma unroll
                for (int mi = 0; mi < 4; mi++)
                    #pragma unroll
                    for (int ni = 0; ni < 4; ni++) {
                        mma_bf16(acc[mi][ni], ah[mi][0], ah[mi][1], ah[mi][2], ah[mi][3], bh[ni][0], bh[ni][1]);
                        mma_bf16(acc[mi][ni], ah[mi][0], ah[mi][1], ah[mi][2], ah[mi][3], bl[ni][0], bl[ni][1]);
                        mma_bf16(acc[mi][ni], al[mi][0], al[mi][1], al[mi][2], al[mi][3], bh[ni][0], bh[ni][1]);
                    }
            }
        }
        __syncthreads();
    }

    if (MODE == 1) {
        #pragma unroll
        for (int mi = 0; mi < 4; mi++) {
            int nr0 = n0 + warp_m * 64 + mi * 16 + r0;
            #pragma unroll
            for (int ni = 0; ni < 4; ni++) {
                int col = c0out + warp_n * 32 + ni * 8 + c0;
                if (nr0 < NN)
                    *reinterpret_cast<float2*>(&g_ab[((size_t)(b * NN + nr0)) * OO2 + col]) =
                        make_float2(acc[mi][ni][0], acc[mi][ni][1]);
                if (nr0 + 8 < NN)
                    *reinterpret_cast<float2*>(&g_ab[((size_t)(b * NN + nr0 + 8)) * OO2 + col]) =
                        make_float2(acc[mi][ni][2], acc[mi][ni][3]);
            }
        }
        return;
    }

    // ---- MODE 0 epilogue: stage dist tile in smem, then per-row/col top-16 ----
    float* sD = reinterpret_cast<float*>(smem);            // [128][129]
    float* sqn_s = reinterpret_cast<float*>(smem + 66048); // 128 floats (rows)
    float* sqm_s = reinterpret_cast<float*>(smem + 66560); // 128 floats (cols)
    if (tid < 128) {
        int rn = n0 + tid;
        sqn_s[tid] = (rn < NN) ? g_sqn[b * NN + rn] : 0.f;
        int cm = c0out + tid;
        sqm_s[tid] = (cm < NN) ? g_sqn[b * NN + cm] : 0.f;
    }
    __syncthreads();
    #pragma unroll
    for (int mi = 0; mi < 4; mi++) {
        int r1 = warp_m * 64 + mi * 16 + r0;
        #pragma unroll
        for (int ni = 0; ni < 4; ni++) {
            int cc = warp_n * 32 + ni * 8 + c0;
            sD[r1 * 129 + cc]           = sqn_s[r1]     + sqm_s[cc]     - 2.f * acc[mi][ni][0];
            sD[r1 * 129 + cc + 1]       = sqn_s[r1]     + sqm_s[cc + 1] - 2.f * acc[mi][ni][1];
            sD[(r1 + 8) * 129 + cc]     = sqn_s[r1 + 8] + sqm_s[cc]     - 2.f * acc[mi][ni][2];
            sD[(r1 + 8) * 129 + cc + 1] = sqn_s[r1 + 8] + sqm_s[cc + 1] - 2.f * acc[mi][ni][3];
        }
    }
    // mask invalid columns (only last column tile)
    if (c0out + 128 > NN) {
        __syncthreads();
        for (int i = tid; i < 128 * 128; i += 256) {
            int r = i >> 7, c = i & 127;
            if (c0out + c >= NN) sD[r * 129 + c] = FINF;
        }
    }
    __syncthreads();

    if (tid < 128) {
        // normal: top-16 of row tid (neighbors c0out..c0out+127)
        int grow = n0 + tid;
        if (grow < NN) {
            Top16 tk;
            tk.init();
            const float* rp = sD + tid * 129;
            #pragma unroll 4
            for (int i = 0; i < 128; i++) tk.push(rp[i], (unsigned)(c0out + i));
            u64* dst = g_pck + ((size_t)(b * NN + grow) * NT + tj) * TT;
            #pragma unroll
            for (int q = 0; q < TT; q++) dst[q] = tk.k[q];
        }
    } else if (ti != tj) {
        // mirror: top-16 of column (tid-128) => row c0out+c, neighbors n0..n0+127
        int c = tid - 128;
        int grow = c0out + c;
        if (grow < NN) {
            Top16 tk;
            tk.init();
            const float* cp = sD + c;
            #pragma unroll 4
            for (int i = 0; i < 128; i++) tk.push(cp[i * 129], (unsigned)(n0 + i));
            u64* dst = g_pck + ((size_t)(b * NN + grow) * NT + ti) * TT;
            #pragma unroll
            for (int q = 0; q < TT; q++) dst[q] = tk.k[q];
        }
    }
}

// ---------------- 4) merge per-tile candidates -> global top-16 ----------------
__global__ __launch_bounds__(256) void mergek_kernel() {
    const int row = blockIdx.x * 8 + (threadIdx.x >> 5);
    const int lane = threadIdx.x & 31;
    const u64* pk = g_pck + (size_t)row * (NT * TT);

    u64 k[13];
    #pragma unroll
    for (int q = 0; q < 13; q++) {
        int p = lane + 32 * q;
        k[q] = (p < NT * TT) ? pk[p] : ~0ull;
    }
    #pragma unroll 1
    for (int t = 0; t < TT; t++) {
        u64 m = k[0];
        int mi = 0;
        #pragma unroll
        for (int q = 1; q < 13; q++)
            if (k[q] < m) { m = k[q]; mi = q; }
        u64 w = m;
        #pragma unroll
        for (int off = 16; off; off >>= 1) {
            u64 o = __shfl_xor_sync(0xFFFFFFFFu, w, off);
            if (o < w) w = o;
        }
        if (lane == 0)
            g_cand[row * TT + t] = (int)(unsigned)(w & 0xFFFFFFFFu);
        if (w == m) {
            #pragma unroll
            for (int q = 0; q < 13; q++)
                if (q == mi) k[q] = ~0ull;
        }
    }
}

// ---------------- 5) exact re-rank (warp per row) ----------------
__global__ void rerank_kernel() {
    int w = threadIdx.x >> 5;
    int lane = threadIdx.x & 31;
    int row = blockIdx.x * 8 + w;
    int b = row / NN;
    int n = row % NN;

    __shared__ float shi[8][TT], slo[8][TT];
    __shared__ int sid[8][TT];

    const float* pn = g_xt + (size_t)row * CC;
    float av[6];
    #pragma unroll
    for (int i = 0; i < 6; i++) av[i] = pn[lane + 32 * i];

    for (int k = 0; k < TT; k++) {
        int j = g_cand[row * TT + k];
        const float* pj = g_xt + ((size_t)b * NN + j) * CC;
        float hi = 0.f, lo = 0.f;
        #pragma unroll
        for (int i = 0; i < 6; i++) {
            float a = av[i];
            float bv = pj[lane + 32 * i];
            float p = a * bv;
            float pe = fmaf(a, bv, -p);
            df_accum(hi, lo, p, pe);
        }
        df_nrm(hi, lo);
        #pragma unroll
        for (int off = 16; off; off >>= 1) {
            float oh = __shfl_down_sync(0xFFFFFFFFu, hi, off);
            float ol = __shfl_down_sync(0xFFFFFFFFu, lo, off);
            df_add2(hi, lo, oh, ol, hi, lo);
        }
        if (lane == 0) {
            float2 qn = g_sqdf[b * NN + n];
            float2 qj = g_sqdf[b * NN + j];
            float th, tl, dh, dl;
            df_add2(qn.x, qn.y, qj.x, qj.y, th, tl);
            df_add2(th, tl, -2.0f * hi, -2.0f * lo, dh, dl);
            shi[w][k] = dh; slo[w][k] = dl; sid[w][k] = j;
        }
    }
    __syncwarp();
    if (lane == 0) {
        #pragma unroll
        for (int i = 1; i < TT; i++) {
            float h = shi[w][i], l = slo[w][i];
            int id = sid[w][i];
            int p = i - 1;
            while (p >= 0) {
                float ph = shi[w][p], pl = slo[w][p];
                int pid = sid[w][p];
                bool gt = (ph > h) || (ph == h && (pl > l || (pl == l && pid > id)));
                if (!gt) break;
                shi[w][p + 1] = ph; slo[w][p + 1] = pl; sid[w][p + 1] = pid;
                p--;
            }
            shi[w][p + 1] = h; slo[w][p + 1] = l; sid[w][p + 1] = id;
        }
        #pragma unroll
        for (int k = 0; k < KK; k++)
            g_idx[row * KK + k] = sid[w][k];
    }
}

// ---------------- 6) gather + affine + max-extremes + 2x GELU (+ edge out) ----------------
__device__ __forceinline__ float gelu_f(float v) {
    return 0.5f * v * (1.0f + erff(v * 0.70710678118654752f));
}
__global__ void fuse_kernel(const float* __restrict__ cb,
                            const float* __restrict__ gamma,
                            const float* __restrict__ beta,
                            float* __restrict__ out,
                            int write_edge) {
    int b = blockIdx.y;
    int n0 = blockIdx.x * 16;
    int o = threadIdx.x;

    __shared__ float sres[16][385];
    __shared__ int sj[16 * KK];

    for (int i = o; i < 16 * KK; i += OO)
        sj[i] = g_idx[(b * NN + n0) * KK + i];
    __syncthreads();

    float gg = gamma[o] / sqrtf(1.0f + 1e-5f);
    float bb = beta[o];
    float cbias = cb[o];
    const float* ab_b = g_ab + (size_t)b * NN * OO2;

    for (int ni = 0; ni < 16; ni++) {
        float a = ab_b[(size_t)(n0 + ni) * OO2 + o] + cbias;
        float smin = FINF, smax = -FINF;
        #pragma unroll
        for (int k = 0; k < KK; k++) {
            int j = sj[ni * KK + k];
            float s = a + ab_b[(size_t)j * OO2 + OO + o];
            smin = fminf(smin, s);
            smax = fmaxf(smax, s);
        }
        float zA = smin * gg + bb;
        float zB = smax * gg + bb;
        sres[ni][o] = fmaxf(gelu_f(zA), gelu_f(zB));
    }
    __syncthreads();

    for (int i = o; i < 16 * OO; i += OO) {
        int oo = i >> 4;
        int ni = i & 15;
        out[((size_t)b * OO + oo) * NN + n0 + ni] = sres[ni][oo];
    }

    if (write_edge) {
        const int total = BB * NN * KK;
        const size_t off = (size_t)BB * OO * NN;
        for (int i = o; i < 16 * KK; i += OO) {
            int ni = i / KK;
            size_t gi = (size_t)(b * NN + n0 + ni) * KK + (i % KK);
            out[off + gi] = (float)sj[i];
            out[off + total + gi] = (float)(n0 + ni);
        }
    }
}

// ---------------- launch ----------------
extern "C" void kernel_launch(void* const* d_in, const int* in_sizes, int n_in,
                              void* d_out, int out_size) {
    const float* x      = (const float*)d_in[0];
    const float* conv_w = (const float*)d_in[1];
    const float* conv_b = (const float*)d_in[2];
    const float* gamma  = (const float*)d_in[3];
    const float* beta   = (const float*)d_in[4];
    float* out = (float*)d_out;

    cudaFuncSetAttribute(mma_kernel<0>, cudaFuncAttributeMaxDynamicSharedMemorySize, SMEM_DYN);
    cudaFuncSetAttribute(mma_kernel<1>, cudaFuncAttributeMaxDynamicSharedMemorySize, SMEM_DYN);

    {
        dim3 grid((NP + 255) / 256, BB);
        normalize_kernel<<<grid, 256>>>(x);
    }
    wprep_kernel<<<(OO2 * CC + 255) / 256, 256>>>(conv_w);
    {
        dim3 grid(NT * (NT + 1) / 2, 1, BB);   // 325 upper-triangle tiles
        mma_kernel<0><<<grid, 256, SMEM_DYN>>>();
    }
    mergek_kernel<<<(BB * NN) / 8, 256>>>();
    rerank_kernel<<<(BB * NN) / 8, 256>>>();
    {
        dim3 grid(OO2 / 128, NP / 128, BB);
        mma_kernel<1><<<grid, 256, SMEM_DYN>>>();
    }
    {
        const long long needed = (long long)BB * OO * NN + 2LL * BB * NN * KK;
        int write_edge = ((long long)out_size >= needed) ? 1 : 0;
        dim3 grid(NN / 16, BB);
        fuse_kernel<<<grid, OO>>>(conv_b, gamma, beta, out, write_edge);
    }
}

// round 14
// speedup vs baseline: 1.5245x; 1.5245x over previous
#include <cuda_runtime.h>
#include <cuda_bf16.h>
#include <math.h>
#include <stdint.h>

#define BB 4
#define CC 192
#define NN 3136
#define NP 3200      // padded rows (25 * 128)
#define KK 9
#define TT 16
#define NT 25
#define OO 384
#define OO2 768
#define FINF 3.402823466e38f

// ---------------- scratch (static device globals) ----------------
__device__ float          g_xt[(size_t)BB * NN * CC];      // fp32 normalized, [row][c]
__device__ __nv_bfloat16  g_nhi[(size_t)BB * NP * CC];     // normalized hi
__device__ __nv_bfloat16  g_nlo[(size_t)BB * NP * CC];     // normalized lo
__device__ __nv_bfloat16  g_xhi[(size_t)BB * NP * CC];     // raw x hi
__device__ __nv_bfloat16  g_xlo[(size_t)BB * NP * CC];     // raw x lo
__device__ __nv_bfloat16  g_whi[OO2 * CC];
__device__ __nv_bfloat16  g_wlo[OO2 * CC];
__device__ float          g_sqn[BB * NN];
__device__ float2         g_sqdf[BB * NN];
__device__ float          g_dist[(size_t)BB * NN * NN];
__device__ int            g_cand[BB * NN * TT];
__device__ int            g_idx[BB * NN * KK];
__device__ float          g_ab[(size_t)BB * NN * OO2];

// ---------------- double-float helpers ----------------
__device__ __forceinline__ void twosum(float a, float b, float& s, float& e) {
    s = a + b;
    float bp = s - a;
    e = (a - (s - bp)) + (b - bp);
}
__device__ __forceinline__ void df_accum(float& hi, float& lo, float p, float pe) {
    float s, e;
    twosum(hi, p, s, e);
    lo += e + pe;
    hi = s;
}
__device__ __forceinline__ void df_nrm(float& hi, float& lo) {
    float s, e;
    twosum(hi, lo, s, e);
    hi = s; lo = e;
}
__device__ __forceinline__ void df_add2(float ah, float al, float bh, float bl, float& h, float& l) {
    float s, e;
    twosum(ah, bh, s, e);
    e += al + bl;
    twosum(s, e, h, l);
}

// ---------------- 1) normalize (vectorized writes) ----------------
__global__ void normalize_kernel(const float* __restrict__ x) {
    int b = blockIdx.y;
    int n = blockIdx.x * 256 + threadIdx.x;
    if (n >= NP) return;
    size_t rowp = ((size_t)b * NP + n) * CC;
    if (n >= NN) {
        uint4 z = make_uint4(0, 0, 0, 0);
        #pragma unroll 4
        for (int i = 0; i < CC / 8; i++) {
            reinterpret_cast<uint4*>(g_nhi + rowp)[i] = z;
            reinterpret_cast<uint4*>(g_nlo + rowp)[i] = z;
            reinterpret_cast<uint4*>(g_xhi + rowp)[i] = z;
            reinterpret_cast<uint4*>(g_xlo + rowp)[i] = z;
        }
        return;
    }
    const float* xb = x + (size_t)b * CC * NN + n;
    float hi = 0.f, lo = 0.f;
    #pragma unroll 2
    for (int c0 = 0; c0 < CC; c0 += 8) {
        float v[8];
        __nv_bfloat16 h8[8], l8[8];
        #pragma unroll
        for (int j = 0; j < 8; j++) v[j] = xb[(size_t)(c0 + j) * NN];
        #pragma unroll
        for (int j = 0; j < 8; j++) {
            float p = v[j] * v[j];
            float pe = fmaf(v[j], v[j], -p);
            df_accum(hi, lo, p, pe);
            h8[j] = __float2bfloat16(v[j]);
            l8[j] = __float2bfloat16(v[j] - __bfloat162float(h8[j]));
        }
        *reinterpret_cast<uint4*>(g_xhi + rowp + c0) = *reinterpret_cast<uint4*>(h8);
        *reinterpret_cast<uint4*>(g_xlo + rowp + c0) = *reinterpret_cast<uint4*>(l8);
    }
    float den = fmaxf(sqrtf(hi + lo), 1e-12f);
    float* xtb = g_xt + ((size_t)b * NN + n) * CC;
    float shi = 0.f, slo = 0.f;
    #pragma unroll 2
    for (int c0 = 0; c0 < CC; c0 += 8) {
        float v[8];
        __nv_bfloat16 h8[8], l8[8];
        #pragma unroll
        for (int j = 0; j < 8; j++) v[j] = __fdiv_rn(xb[(size_t)(c0 + j) * NN], den);
        #pragma unroll
        for (int j = 0; j < 8; j++) {
            float p = v[j] * v[j];
            float pe = fmaf(v[j], v[j], -p);
            df_accum(shi, slo, p, pe);
            h8[j] = __float2bfloat16(v[j]);
            l8[j] = __float2bfloat16(v[j] - __bfloat162float(h8[j]));
        }
        *reinterpret_cast<uint4*>(g_nhi + rowp + c0) = *reinterpret_cast<uint4*>(h8);
        *reinterpret_cast<uint4*>(g_nlo + rowp + c0) = *reinterpret_cast<uint4*>(l8);
        *reinterpret_cast<float4*>(xtb + c0)     = make_float4(v[0], v[1], v[2], v[3]);
        *reinterpret_cast<float4*>(xtb + c0 + 4) = make_float4(v[4], v[5], v[6], v[7]);
    }
    df_nrm(shi, slo);
    g_sqn[b * NN + n] = shi + slo;
    g_sqdf[b * NN + n] = make_float2(shi, slo);
}

// ---------------- 2) weight prep ----------------
__global__ void wprep_kernel(const float* __restrict__ w) {
    int i = blockIdx.x * 256 + threadIdx.x;
    if (i >= OO2 * CC) return;
    int op = i / CC;
    int c = i % CC;
    float v;
    if (op < OO) v = w[op * (2 * CC) + c] - w[op * (2 * CC) + CC + c];
    else         v = w[(op - OO) * (2 * CC) + CC + c];
    __nv_bfloat16 h = __float2bfloat16(v);
    g_whi[i] = h;
    g_wlo[i] = __float2bfloat16(v - __bfloat162float(h));
}

// ---------------- 3) split-bf16 mma.sync GEMM, cp.async pipelined ----------------
__device__ __forceinline__ void mma_bf16(float c[4], uint32_t a0, uint32_t a1, uint32_t a2, uint32_t a3,
                                         uint32_t b0, uint32_t b1) {
    asm volatile("mma.sync.aligned.m16n8k16.row.col.f32.bf16.bf16.f32 "
                 "{%0,%1,%2,%3}, {%4,%5,%6,%7}, {%8,%9}, {%0,%1,%2,%3};"
                 : "+f"(c[0]), "+f"(c[1]), "+f"(c[2]), "+f"(c[3])
                 : "r"(a0), "r"(a1), "r"(a2), "r"(a3), "r"(b0), "r"(b1));
}

__device__ __forceinline__ uint32_t smem_u32(const void* p) {
    uint32_t a;
    asm("{ .reg .u64 t; cvta.to.shared.u64 t, %1; cvt.u32.u64 %0, t; }" : "=r"(a) : "l"(p));
    return a;
}

#define SSTR 40            // smem row stride in bf16 (80B)
#define TILEB 10240        // one 128x40 bf16 tile
#define BUFB  40960        // 4 tiles
#define SMEM_DYN 81920     // 2 buffers; epilogue stage reuses [0, 67072)

template <int MODE>
__global__ __launch_bounds__(256) void mma_kernel() {
    extern __shared__ char smem[];
    const int tid = threadIdx.x;
    const int lane = tid & 31;
    const int wid = tid >> 5;
    const int warp_m = wid & 1;
    const int warp_n = wid >> 1;
    const int b = blockIdx.z;
    const int r0 = lane >> 2;
    const int c0 = (lane & 3) * 2;

    int ti, tj;
    if (MODE == 0) {
        int t = blockIdx.x;
        ti = 0;
        while (t >= NT - ti) { t -= NT - ti; ti++; }
        tj = ti + t;
    } else {
        ti = blockIdx.y;
        tj = blockIdx.x;
    }
    const int n0 = ti * 128;
    const int c0out = tj * 128;

    const __nv_bfloat16 *srcs[4];
    if (MODE == 0) {
        srcs[0] = g_nhi + ((size_t)b * NP + n0) * CC;
        srcs[1] = g_nlo + ((size_t)b * NP + n0) * CC;
        srcs[2] = g_nhi + ((size_t)b * NP + c0out) * CC;
        srcs[3] = g_nlo + ((size_t)b * NP + c0out) * CC;
    } else {
        srcs[0] = g_xhi + ((size_t)b * NP + n0) * CC;
        srcs[1] = g_xlo + ((size_t)b * NP + n0) * CC;
        srcs[2] = g_whi + (size_t)c0out * CC;
        srcs[3] = g_wlo + (size_t)c0out * CC;
    }

    const uint32_t sbase = smem_u32(smem);

    auto issue = [&](int bi, int ch) {
        const int k0 = ch * 32;
        #pragma unroll
        for (int q = 0; q < 8; q++) {
            const int t4 = q >> 1;
            const int row = ((q & 1) * 256 + tid) >> 2;
            const int seg = tid & 3;
            const __nv_bfloat16* src = srcs[t4] + (size_t)row * CC + k0 + seg * 8;
            uint32_t dst = sbase + bi * BUFB + t4 * TILEB + row * 80 + seg * 16;
            asm volatile("cp.async.cg.shared.global [%0], [%1], 16;" :: "r"(dst), "l"(src) : "memory");
        }
        asm volatile("cp.async.commit_group;" ::: "memory");
    };

    float acc[4][4][4];
    #pragma unroll
    for (int i = 0; i < 4; i++)
        #pragma unroll
        for (int j = 0; j < 4; j++)
            #pragma unroll
            for (int q = 0; q < 4; q++) acc[i][j][q] = 0.f;

    issue(0, 0);
    #pragma unroll 1
    for (int ch = 0; ch < 6; ch++) {
        if (ch + 1 < 6) {
            issue((ch + 1) & 1, ch + 1);
            asm volatile("cp.async.wait_group 1;" ::: "memory");
        } else {
            asm volatile("cp.async.wait_group 0;" ::: "memory");
        }
        __syncthreads();
        {
            const int bi = ch & 1;
            const __nv_bfloat16* sAh = reinterpret_cast<const __nv_bfloat16*>(smem + bi * BUFB);
            const __nv_bfloat16* sAl = reinterpret_cast<const __nv_bfloat16*>(smem + bi * BUFB + TILEB);
            const __nv_bfloat16* sBh = reinterpret_cast<const __nv_bfloat16*>(smem + bi * BUFB + 2 * TILEB);
            const __nv_bfloat16* sBl = reinterpret_cast<const __nv_bfloat16*>(smem + bi * BUFB + 3 * TILEB);
            #pragma unroll
            for (int ks = 0; ks < 32; ks += 16) {
                uint32_t ah[4][4], al[4][4], bh[4][2], bl[4][2];
                #pragma unroll
                for (int mi = 0; mi < 4; mi++) {
                    int ar = warp_m * 64 + mi * 16 + r0;
                    const __nv_bfloat16* pa = sAh + ar * SSTR + ks + c0;
                    ah[mi][0] = *reinterpret_cast<const uint32_t*>(pa);
                    ah[mi][1] = *reinterpret_cast<const uint32_t*>(pa + 8 * SSTR);
                    ah[mi][2] = *reinterpret_cast<const uint32_t*>(pa + 8);
                    ah[mi][3] = *reinterpret_cast<const uint32_t*>(pa + 8 * SSTR + 8);
                    const __nv_bfloat16* pl = sAl + ar * SSTR + ks + c0;
                    al[mi][0] = *reinterpret_cast<const uint32_t*>(pl);
                    al[mi][1] = *reinterpret_cast<const uint32_t*>(pl + 8 * SSTR);
                    al[mi][2] = *reinterpret_cast<const uint32_t*>(pl + 8);
                    al[mi][3] = *reinterpret_cast<const uint32_t*>(pl + 8 * SSTR + 8);
                }
                #pragma unroll
                for (int ni = 0; ni < 4; ni++) {
                    int br = warp_n * 32 + ni * 8 + r0;
                    const __nv_bfloat16* pb = sBh + br * SSTR + ks + c0;
                    bh[ni][0] = *reinterpret_cast<const uint32_t*>(pb);
                    bh[ni][1] = *reinterpret_cast<const uint32_t*>(pb + 8);
                    const __nv_bfloat16* pbl = sBl + br * SSTR + ks + c0;
                    bl[ni][0] = *reinterpret_cast<const uint32_t*>(pbl);
                    bl[ni][1] = *reinterpret_cast<const uint32_t*>(pbl + 8);
                }
                #pragma unroll
                for (int mi = 0; mi < 4; mi++)
                    #pragma unroll
                    for (int ni = 0; ni < 4; ni++) {
                        mma_bf16(acc[mi][ni], ah[mi][0], ah[mi][1], ah[mi][2], ah[mi][3], bh[ni][0], bh[ni][1]);
                        mma_bf16(acc[mi][ni], ah[mi][0], ah[mi][1], ah[mi][2], ah[mi][3], bl[ni][0], bl[ni][1]);
                        mma_bf16(acc[mi][ni], al[mi][0], al[mi][1], al[mi][2], al[mi][3], bh[ni][0], bh[ni][1]);
                    }
            }
        }
        __syncthreads();
    }

    if (MODE == 1) {
        #pragma unroll
        for (int mi = 0; mi < 4; mi++) {
            int nr0 = n0 + warp_m * 64 + mi * 16 + r0;
            #pragma unroll
            for (int ni = 0; ni < 4; ni++) {
                int col = c0out + warp_n * 32 + ni * 8 + c0;
                if (nr0 < NN)
                    *reinterpret_cast<float2*>(&g_ab[((size_t)(b * NN + nr0)) * OO2 + col]) =
                        make_float2(acc[mi][ni][0], acc[mi][ni][1]);
                if (nr0 + 8 < NN)
                    *reinterpret_cast<float2*>(&g_ab[((size_t)(b * NN + nr0 + 8)) * OO2 + col]) =
                        make_float2(acc[mi][ni][2], acc[mi][ni][3]);
            }
        }
        return;
    }

    // MODE 0 epilogue: stage full dist tile in smem, write tile + mirror
    float* sD = reinterpret_cast<float*>(smem);            // [128][129]
    float* sqn_s = reinterpret_cast<float*>(smem + 66048);
    float* sqm_s = reinterpret_cast<float*>(smem + 66560);
    if (tid < 128) {
        int rn = n0 + tid;
        sqn_s[tid] = (rn < NN) ? g_sqn[b * NN + rn] : 0.f;
        int cm = c0out + tid;
        sqm_s[tid] = (cm < NN) ? g_sqn[b * NN + cm] : 0.f;
    }
    __syncthreads();
    #pragma unroll
    for (int mi = 0; mi < 4; mi++) {
        int r1 = warp_m * 64 + mi * 16 + r0;
        #pragma unroll
        for (int ni = 0; ni < 4; ni++) {
            int cc = warp_n * 32 + ni * 8 + c0;
            sD[r1 * 129 + cc]           = sqn_s[r1]     + sqm_s[cc]     - 2.f * acc[mi][ni][0];
            sD[r1 * 129 + cc + 1]       = sqn_s[r1]     + sqm_s[cc + 1] - 2.f * acc[mi][ni][1];
            sD[(r1 + 8) * 129 + cc]     = sqn_s[r1 + 8] + sqm_s[cc]     - 2.f * acc[mi][ni][2];
            sD[(r1 + 8) * 129 + cc + 1] = sqn_s[r1 + 8] + sqm_s[cc + 1] - 2.f * acc[mi][ni][3];
        }
    }
    __syncthreads();
    float* dbase = g_dist + (size_t)b * NN * NN;
    #pragma unroll 4
    for (int i = tid; i < 128 * 128; i += 256) {
        int r = i >> 7, c = i & 127;
        int gr = n0 + r, gc = c0out + c;
        if (gr < NN && gc < NN)
            dbase[(size_t)gr * NN + gc] = sD[r * 129 + c];
    }
    if (ti != tj) {
        #pragma unroll 4
        for (int i = tid; i < 128 * 128; i += 256) {
            int dr = i >> 7, el = i & 127;
            int gr = c0out + dr, gc = n0 + el;
            if (gr < NN && gc < NN)
                dbase[(size_t)gr * NN + gc] = sD[el * 129 + dr];
        }
    }
}

// ---------------- 4) top-16: warp per row, float keys + quad prefilter ----------------
__device__ __forceinline__ void ins4f(float v, unsigned pos, float lv[4], unsigned lp[4]) {
    if (v < lv[3]) {
        lv[3] = v; lp[3] = pos;
        if (lv[3] < lv[2]) {
            float tv = lv[2]; lv[2] = lv[3]; lv[3] = tv;
            unsigned tp = lp[2]; lp[2] = lp[3]; lp[3] = tp;
        }
        if (lv[2] < lv[1]) {
            float tv = lv[1]; lv[1] = lv[2]; lv[2] = tv;
            unsigned tp = lp[1]; lp[1] = lp[2]; lp[2] = tp;
        }
        if (lv[1] < lv[0]) {
            float tv = lv[0]; lv[0] = lv[1]; lv[1] = tv;
            unsigned tp = lp[0]; lp[0] = lp[1]; lp[1] = tp;
        }
    }
}

__global__ __launch_bounds__(256) void topk_kernel() {
    const int row = blockIdx.x * 8 + (threadIdx.x >> 5);
    const int lane = threadIdx.x & 31;
    const float4* rowp = reinterpret_cast<const float4*>(g_dist + (size_t)row * NN);

    float    lv[4] = {FINF, FINF, FINF, FINF};
    unsigned lp[4] = {0, 0, 0, 0};
    unsigned msk[4] = {0, 0, 0, 0};

    #pragma unroll 5
    for (int i = 0; i < 25; i++) {
        int p = lane + 32 * i;
        if (p < NN / 4) {
            float4 v = rowp[p];
            // quad prefilter: only enter insertion chains if the quad min beats lv[3]
            float qm = fminf(fminf(v.x, v.y), fminf(v.z, v.w));
            if (qm < lv[3]) {
                ins4f(v.x, i * 4 + 0, lv, lp);
                ins4f(v.y, i * 4 + 1, lv, lp);
                ins4f(v.z, i * 4 + 2, lv, lp);
                ins4f(v.w, i * 4 + 3, lv, lp);
            }
        }
    }

    #pragma unroll 1
    for (int k = 0; k < TT; k++) {
        float w = lv[0];
        #pragma unroll
        for (int off = 16; off; off >>= 1)
            w = fminf(w, __shfl_xor_sync(0xFFFFFFFFu, w, off));
        unsigned myidx = ((lp[0] >> 2) << 7) + 4 * lane + (lp[0] & 3);
        unsigned cidx = (lv[0] == w) ? myidx : 0xFFFFFFFFu;
        #pragma unroll
        for (int off = 16; off; off >>= 1)
            cidx = min(cidx, __shfl_xor_sync(0xFFFFFFFFu, cidx, off));
        if (lane == 0)
            g_cand[row * TT + k] = (int)cidx;
        if (lv[0] == w && myidx == cidx) {
            msk[lp[0] >> 5] |= 1u << (lp[0] & 31);
            lv[0] = lv[1]; lp[0] = lp[1];
            lv[1] = lv[2]; lp[1] = lp[2];
            lv[2] = lv[3]; lp[2] = lp[3];
            lv[3] = FINF;
            if (lv[0] == FINF && k + 1 < TT) {
                #pragma unroll 1
                for (int i = 0; i < 25; i++) {
                    int p = lane + 32 * i;
                    if (p < NN / 4) {
                        float4 v = rowp[p];
                        float vv[4] = {v.x, v.y, v.z, v.w};
                        #pragma unroll
                        for (int j = 0; j < 4; j++) {
                            unsigned pos = i * 4 + j;
                            if ((msk[pos >> 5] >> (pos & 31)) & 1u) continue;
                            ins4f(vv[j], pos, lv, lp);
                        }
                    }
                }
            }
        }
    }
}

// ---------------- 5) exact re-rank (warp per row) ----------------
__global__ void rerank_kernel() {
    int w = threadIdx.x >> 5;
    int lane = threadIdx.x & 31;
    int row = blockIdx.x * 8 + w;
    int b = row / NN;
    int n = row % NN;

    __shared__ float shi[8][TT], slo[8][TT];
    __shared__ int sid[8][TT];

    const float* pn = g_xt + (size_t)row * CC;
    float av[6];
    #pragma unroll
    for (int i = 0; i < 6; i++) av[i] = pn[lane + 32 * i];

    for (int k = 0; k < TT; k++) {
        int j = g_cand[row * TT + k];
        const float* pj = g_xt + ((size_t)b * NN + j) * CC;
        float hi = 0.f, lo = 0.f;
        #pragma unroll
        for (int i = 0; i < 6; i++) {
            float a = av[i];
            float bv = pj[lane + 32 * i];
            float p = a * bv;
            float pe = fmaf(a, bv, -p);
            df_accum(hi, lo, p, pe);
        }
        df_nrm(hi, lo);
        #pragma unroll
        for (int off = 16; off; off >>= 1) {
            float oh = __shfl_down_sync(0xFFFFFFFFu, hi, off);
            float ol = __shfl_down_sync(0xFFFFFFFFu, lo, off);
            df_add2(hi, lo, oh, ol, hi, lo);
        }
        if (lane == 0) {
            float2 qn = g_sqdf[b * NN + n];
            float2 qj = g_sqdf[b * NN + j];
            float th, tl, dh, dl;
            df_add2(qn.x, qn.y, qj.x, qj.y, th, tl);
            df_add2(th, tl, -2.0f * hi, -2.0f * lo, dh, dl);
            shi[w][k] = dh; slo[w][k] = dl; sid[w][k] = j;
        }
    }
    __syncwarp();
    if (lane == 0) {
        #pragma unroll
        for (int i = 1; i < TT; i++) {
            float h = shi[w][i], l = slo[w][i];
            int id = sid[w][i];
            int p = i - 1;
            while (p >= 0) {
                float ph = shi[w][p], pl = slo[w][p];
                int pid = sid[w][p];
                bool gt = (ph > h) || (ph == h && (pl > l || (pl == l && pid > id)));
                if (!gt) break;
                shi[w][p + 1] = ph; slo[w][p + 1] = pl; sid[w][p + 1] = pid;
                p--;
            }
            shi[w][p + 1] = h; slo[w][p + 1] = l; sid[w][p + 1] = id;
        }
        #pragma unroll
        for (int k = 0; k < KK; k++)
            g_idx[row * KK + k] = sid[w][k];
    }
}

// ---------------- 6) gather + affine + max-extremes + 2x GELU (+ edge out) ----------------
__device__ __forceinline__ float gelu_f(float v) {
    return 0.5f * v * (1.0f + erff(v * 0.70710678118654752f));
}
__global__ void fuse_kernel(const float* __restrict__ cb,
                            const float* __restrict__ gamma,
                            const float* __restrict__ beta,
                            float* __restrict__ out,
                            int write_edge) {
    int b = blockIdx.y;
    int n0 = blockIdx.x * 16;
    int o = threadIdx.x;

    __shared__ float sres[16][385];
    __shared__ int sj[16 * KK];

    for (int i = o; i < 16 * KK; i += OO)
        sj[i] = g_idx[(b * NN + n0) * KK + i];
    __syncthreads();

    float gg = gamma[o] / sqrtf(1.0f + 1e-5f);
    float bb = beta[o];
    float cbias = cb[o];
    const float* ab_b = g_ab + (size_t)b * NN * OO2;

    for (int ni = 0; ni < 16; ni++) {
        float a = ab_b[(size_t)(n0 + ni) * OO2 + o] + cbias;
        float smin = FINF, smax = -FINF;
        #pragma unroll
        for (int k = 0; k < KK; k++) {
            int j = sj[ni * KK + k];
            float s = a + ab_b[(size_t)j * OO2 + OO + o];
            smin = fminf(smin, s);
            smax = fmaxf(smax, s);
        }
        float zA = smin * gg + bb;
        float zB = smax * gg + bb;
        sres[ni][o] = fmaxf(gelu_f(zA), gelu_f(zB));
    }
    __syncthreads();

    for (int i = o; i < 16 * OO; i += OO) {
        int oo = i >> 4;
        int ni = i & 15;
        out[((size_t)b * OO + oo) * NN + n0 + ni] = sres[ni][oo];
    }

    if (write_edge) {
        const int total = BB * NN * KK;
        const size_t off = (size_t)BB * OO * NN;
        for (int i = o; i < 16 * KK; i += OO) {
            int ni = i / KK;
            size_t gi = (size_t)(b * NN + n0 + ni) * KK + (i % KK);
            out[off + gi] = (float)sj[i];
            out[off + total + gi] = (float)(n0 + ni);
        }
    }
}

// ---------------- launch ----------------
extern "C" void kernel_launch(void* const* d_in, const int* in_sizes, int n_in,
                              void* d_out, int out_size) {
    const float* x      = (const float*)d_in[0];
    const float* conv_w = (const float*)d_in[1];
    const float* conv_b = (const float*)d_in[2];
    const float* gamma  = (const float*)d_in[3];
    const float* beta   = (const float*)d_in[4];
    float* out = (float*)d_out;

    cudaFuncSetAttribute(mma_kernel<0>, cudaFuncAttributeMaxDynamicSharedMemorySize, SMEM_DYN);
    cudaFuncSetAttribute(mma_kernel<1>, cudaFuncAttributeMaxDynamicSharedMemorySize, SMEM_DYN);

    {
        dim3 grid((NP + 255) / 256, BB);
        normalize_kernel<<<grid, 256>>>(x);
    }
    wprep_kernel<<<(OO2 * CC + 255) / 256, 256>>>(conv_w);
    {
        dim3 grid(NT * (NT + 1) / 2, 1, BB);
        mma_kernel<0><<<grid, 256, SMEM_DYN>>>();
    }
    topk_kernel<<<(BB * NN) / 8, 256>>>();
    rerank_kernel<<<(BB * NN) / 8, 256>>>();
    {
        dim3 grid(OO2 / 128, NP / 128, BB);
        mma_kernel<1><<<grid, 256, SMEM_DYN>>>();
    }
    {
        const long long needed = (long long)BB * OO * NN + 2LL * BB * NN * KK;
        int write_edge = ((long long)out_size >= needed) ? 1 : 0;
        dim3 grid(NN / 16, BB);
        fuse_kernel<<<grid, OO>>>(conv_b, gamma, beta, out, write_edge);
    }
}

// round 15
// speedup vs baseline: 1.6123x; 1.0576x over previous
#include <cuda_runtime.h>
#include <cuda_bf16.h>
#include <math.h>
#include <stdint.h>

#define BB 4
#define CC 192
#define NN 3136
#define NP 3200      // padded rows (25 * 128)
#define KK 9
#define TT 16
#define NT 25
#define OO 384
#define OO2 768
#define FINF 3.402823466e38f

// ---------------- scratch (static device globals) ----------------
__device__ float          g_xt[(size_t)BB * NN * CC];      // fp32 normalized, [row][c]
__device__ __nv_bfloat16  g_nhi[(size_t)BB * NP * CC];     // normalized hi
__device__ __nv_bfloat16  g_nlo[(size_t)BB * NP * CC];     // normalized lo
__device__ __nv_bfloat16  g_xhi[(size_t)BB * NP * CC];     // raw x hi
__device__ __nv_bfloat16  g_xlo[(size_t)BB * NP * CC];     // raw x lo
__device__ __nv_bfloat16  g_whi[OO2 * CC];
__device__ __nv_bfloat16  g_wlo[OO2 * CC];
__device__ float          g_sqn[BB * NN];
__device__ float2         g_sqdf[BB * NN];
__device__ float          g_dist[(size_t)BB * NN * NN];
__device__ int            g_cand[BB * NN * TT];
__device__ int            g_idx[BB * NN * KK];
__device__ float          g_ab[(size_t)BB * NN * OO2];

// ---------------- ordered-float encoding ----------------
__device__ __forceinline__ unsigned encf(float v) {
    unsigned u = __float_as_uint(v);
    return u ^ ((u & 0x80000000u) ? 0xFFFFFFFFu : 0x80000000u);
}

// ---------------- double-float helpers ----------------
__device__ __forceinline__ void twosum(float a, float b, float& s, float& e) {
    s = a + b;
    float bp = s - a;
    e = (a - (s - bp)) + (b - bp);
}
__device__ __forceinline__ void df_accum(float& hi, float& lo, float p, float pe) {
    float s, e;
    twosum(hi, p, s, e);
    lo += e + pe;
    hi = s;
}
__device__ __forceinline__ void df_nrm(float& hi, float& lo) {
    float s, e;
    twosum(hi, lo, s, e);
    hi = s; lo = e;
}
__device__ __forceinline__ void df_add2(float ah, float al, float bh, float bl, float& h, float& l) {
    float s, e;
    twosum(ah, bh, s, e);
    e += al + bl;
    twosum(s, e, h, l);
}

// ---------------- 1) normalize (vectorized writes) ----------------
__global__ void normalize_kernel(const float* __restrict__ x) {
    int b = blockIdx.y;
    int n = blockIdx.x * 256 + threadIdx.x;
    if (n >= NP) return;
    size_t rowp = ((size_t)b * NP + n) * CC;
    if (n >= NN) {
        uint4 z = make_uint4(0, 0, 0, 0);
        #pragma unroll 4
        for (int i = 0; i < CC / 8; i++) {
            reinterpret_cast<uint4*>(g_nhi + rowp)[i] = z;
            reinterpret_cast<uint4*>(g_nlo + rowp)[i] = z;
            reinterpret_cast<uint4*>(g_xhi + rowp)[i] = z;
            reinterpret_cast<uint4*>(g_xlo + rowp)[i] = z;
        }
        return;
    }
    const float* xb = x + (size_t)b * CC * NN + n;
    float hi = 0.f, lo = 0.f;
    #pragma unroll 2
    for (int c0 = 0; c0 < CC; c0 += 8) {
        float v[8];
        __nv_bfloat16 h8[8], l8[8];
        #pragma unroll
        for (int j = 0; j < 8; j++) v[j] = xb[(size_t)(c0 + j) * NN];
        #pragma unroll
        for (int j = 0; j < 8; j++) {
            float p = v[j] * v[j];
            float pe = fmaf(v[j], v[j], -p);
            df_accum(hi, lo, p, pe);
            h8[j] = __float2bfloat16(v[j]);
            l8[j] = __float2bfloat16(v[j] - __bfloat162float(h8[j]));
        }
        *reinterpret_cast<uint4*>(g_xhi + rowp + c0) = *reinterpret_cast<uint4*>(h8);
        *reinterpret_cast<uint4*>(g_xlo + rowp + c0) = *reinterpret_cast<uint4*>(l8);
    }
    float den = fmaxf(sqrtf(hi + lo), 1e-12f);
    float* xtb = g_xt + ((size_t)b * NN + n) * CC;
    float shi = 0.f, slo = 0.f;
    #pragma unroll 2
    for (int c0 = 0; c0 < CC; c0 += 8) {
        float v[8];
        __nv_bfloat16 h8[8], l8[8];
        #pragma unroll
        for (int j = 0; j < 8; j++) v[j] = __fdiv_rn(xb[(size_t)(c0 + j) * NN], den);
        #pragma unroll
        for (int j = 0; j < 8; j++) {
            float p = v[j] * v[j];
            float pe = fmaf(v[j], v[j], -p);
            df_accum(shi, slo, p, pe);
            h8[j] = __float2bfloat16(v[j]);
            l8[j] = __float2bfloat16(v[j] - __bfloat162float(h8[j]));
        }
        *reinterpret_cast<uint4*>(g_nhi + rowp + c0) = *reinterpret_cast<uint4*>(h8);
        *reinterpret_cast<uint4*>(g_nlo + rowp + c0) = *reinterpret_cast<uint4*>(l8);
        *reinterpret_cast<float4*>(xtb + c0)     = make_float4(v[0], v[1], v[2], v[3]);
        *reinterpret_cast<float4*>(xtb + c0 + 4) = make_float4(v[4], v[5], v[6], v[7]);
    }
    df_nrm(shi, slo);
    g_sqn[b * NN + n] = shi + slo;
    g_sqdf[b * NN + n] = make_float2(shi, slo);
}

// ---------------- 2) weight prep ----------------
__global__ void wprep_kernel(const float* __restrict__ w) {
    int i = blockIdx.x * 256 + threadIdx.x;
    if (i >= OO2 * CC) return;
    int op = i / CC;
    int c = i % CC;
    float v;
    if (op < OO) v = w[op * (2 * CC) + c] - w[op * (2 * CC) + CC + c];
    else         v = w[(op - OO) * (2 * CC) + CC + c];
    __nv_bfloat16 h = __float2bfloat16(v);
    g_whi[i] = h;
    g_wlo[i] = __float2bfloat16(v - __bfloat162float(h));
}

// ---------------- 3) split-bf16 mma.sync GEMM, cp.async pipelined ----------------
__device__ __forceinline__ void mma_bf16(float c[4], uint32_t a0, uint32_t a1, uint32_t a2, uint32_t a3,
                                         uint32_t b0, uint32_t b1) {
    asm volatile("mma.sync.aligned.m16n8k16.row.col.f32.bf16.bf16.f32 "
                 "{%0,%1,%2,%3}, {%4,%5,%6,%7}, {%8,%9}, {%0,%1,%2,%3};"
                 : "+f"(c[0]), "+f"(c[1]), "+f"(c[2]), "+f"(c[3])
                 : "r"(a0), "r"(a1), "r"(a2), "r"(a3), "r"(b0), "r"(b1));
}

__device__ __forceinline__ uint32_t smem_u32(const void* p) {
    uint32_t a;
    asm("{ .reg .u64 t; cvta.to.shared.u64 t, %1; cvt.u32.u64 %0, t; }" : "=r"(a) : "l"(p));
    return a;
}

#define SSTR 40            // smem row stride in bf16 (80B)
#define TILEB 10240        // one 128x40 bf16 tile
#define BUFB  40960        // 4 tiles
#define SMEM_DYN 81920     // 2 buffers; epilogue stage reuses [0, 67072)

template <int MODE>
__global__ __launch_bounds__(256) void mma_kernel() {
    extern __shared__ char smem[];
    const int tid = threadIdx.x;
    const int lane = tid & 31;
    const int wid = tid >> 5;
    const int warp_m = wid & 1;
    const int warp_n = wid >> 1;
    const int b = blockIdx.z;
    const int r0 = lane >> 2;
    const int c0 = (lane & 3) * 2;

    int ti, tj;
    if (MODE == 0) {
        int t = blockIdx.x;
        ti = 0;
        while (t >= NT - ti) { t -= NT - ti; ti++; }
        tj = ti + t;
    } else {
        ti = blockIdx.y;
        tj = blockIdx.x;
    }
    const int n0 = ti * 128;
    const int c0out = tj * 128;

    const __nv_bfloat16 *srcs[4];
    if (MODE == 0) {
        srcs[0] = g_nhi + ((size_t)b * NP + n0) * CC;
        srcs[1] = g_nlo + ((size_t)b * NP + n0) * CC;
        srcs[2] = g_nhi + ((size_t)b * NP + c0out) * CC;
        srcs[3] = g_nlo + ((size_t)b * NP + c0out) * CC;
    } else {
        srcs[0] = g_xhi + ((size_t)b * NP + n0) * CC;
        srcs[1] = g_xlo + ((size_t)b * NP + n0) * CC;
        srcs[2] = g_whi + (size_t)c0out * CC;
        srcs[3] = g_wlo + (size_t)c0out * CC;
    }

    const uint32_t sbase = smem_u32(smem);

    auto issue = [&](int bi, int ch) {
        const int k0 = ch * 32;
        #pragma unroll
        for (int q = 0; q < 8; q++) {
            const int t4 = q >> 1;
            const int row = ((q & 1) * 256 + tid) >> 2;
            const int seg = tid & 3;
            const __nv_bfloat16* src = srcs[t4] + (size_t)row * CC + k0 + seg * 8;
            uint32_t dst = sbase + bi * BUFB + t4 * TILEB + row * 80 + seg * 16;
            asm volatile("cp.async.cg.shared.global [%0], [%1], 16;" :: "r"(dst), "l"(src) : "memory");
        }
        asm volatile("cp.async.commit_group;" ::: "memory");
    };

    float acc[4][4][4];
    #pragma unroll
    for (int i = 0; i < 4; i++)
        #pragma unroll
        for (int j = 0; j < 4; j++)
            #pragma unroll
            for (int q = 0; q < 4; q++) acc[i][j][q] = 0.f;

    issue(0, 0);
    #pragma unroll 1
    for (int ch = 0; ch < 6; ch++) {
        if (ch + 1 < 6) {
            issue((ch + 1) & 1, ch + 1);
            asm volatile("cp.async.wait_group 1;" ::: "memory");
        } else {
            asm volatile("cp.async.wait_group 0;" ::: "memory");
        }
        __syncthreads();
        {
            const int bi = ch & 1;
            const __nv_bfloat16* sAh = reinterpret_cast<const __nv_bfloat16*>(smem + bi * BUFB);
            const __nv_bfloat16* sAl = reinterpret_cast<const __nv_bfloat16*>(smem + bi * BUFB + TILEB);
            const __nv_bfloat16* sBh = reinterpret_cast<const __nv_bfloat16*>(smem + bi * BUFB + 2 * TILEB);
            const __nv_bfloat16* sBl = reinterpret_cast<const __nv_bfloat16*>(smem + bi * BUFB + 3 * TILEB);
            #pragma unroll
            for (int ks = 0; ks < 32; ks += 16) {
                uint32_t ah[4][4], al[4][4], bh[4][2], bl[4][2];
                #pragma unroll
                for (int mi = 0; mi < 4; mi++) {
                    int ar = warp_m * 64 + mi * 16 + r0;
                    const __nv_bfloat16* pa = sAh + ar * SSTR + ks + c0;
                    ah[mi][0] = *reinterpret_cast<const uint32_t*>(pa);
                    ah[mi][1] = *reinterpret_cast<const uint32_t*>(pa + 8 * SSTR);
                    ah[mi][2] = *reinterpret_cast<const uint32_t*>(pa + 8);
                    ah[mi][3] = *reinterpret_cast<const uint32_t*>(pa + 8 * SSTR + 8);
                    const __nv_bfloat16* pl = sAl + ar * SSTR + ks + c0;
                    al[mi][0] = *reinterpret_cast<const uint32_t*>(pl);
                    al[mi][1] = *reinterpret_cast<const uint32_t*>(pl + 8 * SSTR);
                    al[mi][2] = *reinterpret_cast<const uint32_t*>(pl + 8);
                    al[mi][3] = *reinterpret_cast<const uint32_t*>(pl + 8 * SSTR + 8);
                }
                #pragma unroll
                for (int ni = 0; ni < 4; ni++) {
                    int br = warp_n * 32 + ni * 8 + r0;
                    const __nv_bfloat16* pb = sBh + br * SSTR + ks + c0;
                    bh[ni][0] = *reinterpret_cast<const uint32_t*>(pb);
                    bh[ni][1] = *reinterpret_cast<const uint32_t*>(pb + 8);
                    const __nv_bfloat16* pbl = sBl + br * SSTR + ks + c0;
                    bl[ni][0] = *reinterpret_cast<const uint32_t*>(pbl);
                    bl[ni][1] = *reinterpret_cast<const uint32_t*>(pbl + 8);
                }
                #pragma unroll
                for (int mi = 0; mi < 4; mi++)
                    #pragma unroll
                    for (int ni = 0; ni < 4; ni++) {
                        mma_bf16(acc[mi][ni], ah[mi][0], ah[mi][1], ah[mi][2], ah[mi][3], bh[ni][0], bh[ni][1]);
                        mma_bf16(acc[mi][ni], ah[mi][0], ah[mi][1], ah[mi][2], ah[mi][3], bl[ni][0], bl[ni][1]);
                        mma_bf16(acc[mi][ni], al[mi][0], al[mi][1], al[mi][2], al[mi][3], bh[ni][0], bh[ni][1]);
                    }
            }
        }
        __syncthreads();
    }

    if (MODE == 1) {
        #pragma unroll
        for (int mi = 0; mi < 4; mi++) {
            int nr0 = n0 + warp_m * 64 + mi * 16 + r0;
            #pragma unroll
            for (int ni = 0; ni < 4; ni++) {
                int col = c0out + warp_n * 32 + ni * 8 + c0;
                if (nr0 < NN)
                    *reinterpret_cast<float2*>(&g_ab[((size_t)(b * NN + nr0)) * OO2 + col]) =
                        make_float2(acc[mi][ni][0], acc[mi][ni][1]);
                if (nr0 + 8 < NN)
                    *reinterpret_cast<float2*>(&g_ab[((size_t)(b * NN + nr0 + 8)) * OO2 + col]) =
                        make_float2(acc[mi][ni][2], acc[mi][ni][3]);
            }
        }
        return;
    }

    // MODE 0 epilogue: stage full dist tile in smem, write tile + mirror
    float* sD = reinterpret_cast<float*>(smem);            // [128][129]
    float* sqn_s = reinterpret_cast<float*>(smem + 66048);
    float* sqm_s = reinterpret_cast<float*>(smem + 66560);
    if (tid < 128) {
        int rn = n0 + tid;
        sqn_s[tid] = (rn < NN) ? g_sqn[b * NN + rn] : 0.f;
        int cm = c0out + tid;
        sqm_s[tid] = (cm < NN) ? g_sqn[b * NN + cm] : 0.f;
    }
    __syncthreads();
    #pragma unroll
    for (int mi = 0; mi < 4; mi++) {
        int r1 = warp_m * 64 + mi * 16 + r0;
        #pragma unroll
        for (int ni = 0; ni < 4; ni++) {
            int cc = warp_n * 32 + ni * 8 + c0;
            sD[r1 * 129 + cc]           = sqn_s[r1]     + sqm_s[cc]     - 2.f * acc[mi][ni][0];
            sD[r1 * 129 + cc + 1]       = sqn_s[r1]     + sqm_s[cc + 1] - 2.f * acc[mi][ni][1];
            sD[(r1 + 8) * 129 + cc]     = sqn_s[r1 + 8] + sqm_s[cc]     - 2.f * acc[mi][ni][2];
            sD[(r1 + 8) * 129 + cc + 1] = sqn_s[r1 + 8] + sqm_s[cc + 1] - 2.f * acc[mi][ni][3];
        }
    }
    __syncthreads();
    float* dbase = g_dist + (size_t)b * NN * NN;
    #pragma unroll 4
    for (int i = tid; i < 128 * 128; i += 256) {
        int r = i >> 7, c = i & 127;
        int gr = n0 + r, gc = c0out + c;
        if (gr < NN && gc < NN)
            dbase[(size_t)gr * NN + gc] = sD[r * 129 + c];
    }
    if (ti != tj) {
        #pragma unroll 4
        for (int i = tid; i < 128 * 128; i += 256) {
            int dr = i >> 7, el = i & 127;
            int gr = c0out + dr, gc = n0 + el;
            if (gr < NN && gc < NN)
                dbase[(size_t)gr * NN + gc] = sD[el * 129 + dr];
        }
    }
}

// ---------------- 4) top-16: warp per row, staged loads (high MLP) + REDUX extract ----------------
__device__ __forceinline__ void ins4f(float v, unsigned pos, float lv[4], unsigned lp[4]) {
    if (v < lv[3]) {
        lv[3] = v; lp[3] = pos;
        if (lv[3] < lv[2]) {
            float tv = lv[2]; lv[2] = lv[3]; lv[3] = tv;
            unsigned tp = lp[2]; lp[2] = lp[3]; lp[3] = tp;
        }
        if (lv[2] < lv[1]) {
            float tv = lv[1]; lv[1] = lv[2]; lv[2] = tv;
            unsigned tp = lp[1]; lp[1] = lp[2]; lp[2] = tp;
        }
        if (lv[1] < lv[0]) {
            float tv = lv[0]; lv[0] = lv[1]; lv[1] = tv;
            unsigned tp = lp[0]; lp[0] = lp[1]; lp[1] = tp;
        }
    }
}

__global__ __launch_bounds__(256) void topk_kernel() {
    const int row = blockIdx.x * 8 + (threadIdx.x >> 5);
    const int lane = threadIdx.x & 31;
    const float4* rowp = reinterpret_cast<const float4*>(g_dist + (size_t)row * NN);

    float    lv[4] = {FINF, FINF, FINF, FINF};
    unsigned lp[4] = {0, 0, 0, 0};
    unsigned msk[4] = {0, 0, 0, 0};

    // main scan: 24 full strips of 32 float4, staged 8 at a time for MLP
    #pragma unroll 1
    for (int base = 0; base < 24; base += 8) {
        float4 v[8];
        #pragma unroll
        for (int t = 0; t < 8; t++)
            v[t] = rowp[lane + 32 * (base + t)];
        #pragma unroll
        for (int t = 0; t < 8; t++) {
            unsigned pos = (base + t) * 4;
            ins4f(v[t].x, pos + 0, lv, lp);
            ins4f(v[t].y, pos + 1, lv, lp);
            ins4f(v[t].z, pos + 2, lv, lp);
            ins4f(v[t].w, pos + 3, lv, lp);
        }
    }
    // tail strip i=24: p = lane + 768 < 784 -> lanes 0..15
    if (lane < 16) {
        float4 v = rowp[lane + 768];
        ins4f(v.x, 96, lv, lp);
        ins4f(v.y, 97, lv, lp);
        ins4f(v.z, 98, lv, lp);
        ins4f(v.w, 99, lv, lp);
    }

    #pragma unroll 1
    for (int k = 0; k < TT; k++) {
        unsigned e0 = encf(lv[0]);
        unsigned w = __reduce_min_sync(0xFFFFFFFFu, e0);
        unsigned myidx = ((lp[0] >> 2) << 7) + 4 * lane + (lp[0] & 3);
        unsigned ci = (e0 == w) ? myidx : 0xFFFFFFFFu;
        unsigned cidx = __reduce_min_sync(0xFFFFFFFFu, ci);
        if (lane == 0)
            g_cand[row * TT + k] = (int)cidx;
        if (e0 == w && myidx == cidx) {
            msk[lp[0] >> 5] |= 1u << (lp[0] & 31);
            lv[0] = lv[1]; lp[0] = lp[1];
            lv[1] = lv[2]; lp[1] = lp[2];
            lv[2] = lv[3]; lp[2] = lp[3];
            lv[3] = FINF;
            if (lv[0] == FINF && k + 1 < TT) {
                // rare: rebuild local top-4 among unpopped elements
                #pragma unroll 1
                for (int i = 0; i < 25; i++) {
                    int p = lane + 32 * i;
                    if (p < NN / 4) {
                        float4 v = rowp[p];
                        float vv[4] = {v.x, v.y, v.z, v.w};
                        #pragma unroll
                        for (int j = 0; j < 4; j++) {
                            unsigned pos = i * 4 + j;
                            if ((msk[pos >> 5] >> (pos & 31)) & 1u) continue;
                            ins4f(vv[j], pos, lv, lp);
                        }
                    }
                }
            }
        }
    }
}

// ---------------- 5) exact re-rank (warp per row) ----------------
__global__ void rerank_kernel() {
    int w = threadIdx.x >> 5;
    int lane = threadIdx.x & 31;
    int row = blockIdx.x * 8 + w;
    int b = row / NN;
    int n = row % NN;

    __shared__ float shi[8][TT], slo[8][TT];
    __shared__ int sid[8][TT];

    const float* pn = g_xt + (size_t)row * CC;
    float av[6];
    #pragma unroll
    for (int i = 0; i < 6; i++) av[i] = pn[lane + 32 * i];

    for (int k = 0; k < TT; k++) {
        int j = g_cand[row * TT + k];
        const float* pj = g_xt + ((size_t)b * NN + j) * CC;
        float hi = 0.f, lo = 0.f;
        #pragma unroll
        for (int i = 0; i < 6; i++) {
            float a = av[i];
            float bv = pj[lane + 32 * i];
            float p = a * bv;
            float pe = fmaf(a, bv, -p);
            df_accum(hi, lo, p, pe);
        }
        df_nrm(hi, lo);
        #pragma unroll
        for (int off = 16; off; off >>= 1) {
            float oh = __shfl_down_sync(0xFFFFFFFFu, hi, off);
            float ol = __shfl_down_sync(0xFFFFFFFFu, lo, off);
            df_add2(hi, lo, oh, ol, hi, lo);
        }
        if (lane == 0) {
            float2 qn = g_sqdf[b * NN + n];
            float2 qj = g_sqdf[b * NN + j];
            float th, tl, dh, dl;
            df_add2(qn.x, qn.y, qj.x, qj.y, th, tl);
            df_add2(th, tl, -2.0f * hi, -2.0f * lo, dh, dl);
            shi[w][k] = dh; slo[w][k] = dl; sid[w][k] = j;
        }
    }
    __syncwarp();
    if (lane == 0) {
        #pragma unroll
        for (int i = 1; i < TT; i++) {
            float h = shi[w][i], l = slo[w][i];
            int id = sid[w][i];
            int p = i - 1;
            while (p >= 0) {
                float ph = shi[w][p], pl = slo[w][p];
                int pid = sid[w][p];
                bool gt = (ph > h) || (ph == h && (pl > l || (pl == l && pid > id)));
                if (!gt) break;
                shi[w][p + 1] = ph; slo[w][p + 1] = pl; sid[w][p + 1] = pid;
                p--;
            }
            shi[w][p + 1] = h; slo[w][p + 1] = l; sid[w][p + 1] = id;
        }
        #pragma unroll
        for (int k = 0; k < KK; k++)
            g_idx[row * KK + k] = sid[w][k];
    }
}

// ---------------- 6) gather + affine + max-extremes + 2x GELU (+ edge out) ----------------
__device__ __forceinline__ float gelu_f(float v) {
    return 0.5f * v * (1.0f + erff(v * 0.70710678118654752f));
}
__global__ void fuse_kernel(const float* __restrict__ cb,
                            const float* __restrict__ gamma,
                            const float* __restrict__ beta,
                            float* __restrict__ out,
                            int write_edge) {
    int b = blockIdx.y;
    int n0 = blockIdx.x * 16;
    int o = threadIdx.x;

    __shared__ float sres[16][385];
    __shared__ int sj[16 * KK];

    for (int i = o; i < 16 * KK; i += OO)
        sj[i] = g_idx[(b * NN + n0) * KK + i];
    __syncthreads();

    float gg = gamma[o] / sqrtf(1.0f + 1e-5f);
    float bb = beta[o];
    float cbias = cb[o];
    const float* ab_b = g_ab + (size_t)b * NN * OO2;

    for (int ni = 0; ni < 16; ni++) {
        float a = ab_b[(size_t)(n0 + ni) * OO2 + o] + cbias;
        float smin = FINF, smax = -FINF;
        #pragma unroll
        for (int k = 0; k < KK; k++) {
            int j = sj[ni * KK + k];
            float s = a + ab_b[(size_t)j * OO2 + OO + o];
            smin = fminf(smin, s);
            smax = fmaxf(smax, s);
        }
        float zA = smin * gg + bb;
        float zB = smax * gg + bb;
        sres[ni][o] = fmaxf(gelu_f(zA), gelu_f(zB));
    }
    __syncthreads();

    for (int i = o; i < 16 * OO; i += OO) {
        int oo = i >> 4;
        int ni = i & 15;
        out[((size_t)b * OO + oo) * NN + n0 + ni] = sres[ni][oo];
    }

    if (write_edge) {
        const int total = BB * NN * KK;
        const size_t off = (size_t)BB * OO * NN;
        for (int i = o; i < 16 * KK; i += OO) {
            int ni = i / KK;
            size_t gi = (size_t)(b * NN + n0 + ni) * KK + (i % KK);
            out[off + gi] = (float)sj[i];
            out[off + total + gi] = (float)(n0 + ni);
        }
    }
}

// ---------------- launch ----------------
extern "C" void kernel_launch(void* const* d_in, const int* in_sizes, int n_in,
                              void* d_out, int out_size) {
    const float* x      = (const float*)d_in[0];
    const float* conv_w = (const float*)d_in[1];
    const float* conv_b = (const float*)d_in[2];
    const float* gamma  = (const float*)d_in[3];
    const float* beta   = (const float*)d_in[4];
    float* out = (float*)d_out;

    cudaFuncSetAttribute(mma_kernel<0>, cudaFuncAttributeMaxDynamicSharedMemorySize, SMEM_DYN);
    cudaFuncSetAttribute(mma_kernel<1>, cudaFuncAttributeMaxDynamicSharedMemorySize, SMEM_DYN);

    {
        dim3 grid((NP + 255) / 256, BB);
        normalize_kernel<<<grid, 256>>>(x);
    }
    wprep_kernel<<<(OO2 * CC + 255) / 256, 256>>>(conv_w);
    {
        dim3 grid(NT * (NT + 1) / 2, 1, BB);
        mma_kernel<0><<<grid, 256, SMEM_DYN>>>();
    }
    topk_kernel<<<(BB * NN) / 8, 256>>>();
    rerank_kernel<<<(BB * NN) / 8, 256>>>();
    {
        dim3 grid(OO2 / 128, NP / 128, BB);
        mma_kernel<1><<<grid, 256, SMEM_DYN>>>();
    }
    {
        const long long needed = (long long)BB * OO * NN + 2LL * BB * NN * KK;
        int write_edge = ((long long)out_size >= needed) ? 1 : 0;
        dim3 grid(NN / 16, BB);
        fuse_kernel<<<grid, OO>>>(conv_b, gamma, beta, out, write_edge);
    }
}